// round 2
// baseline (speedup 1.0000x reference)
#include <cuda_runtime.h>
#include <cstdint>
#include <cstddef>

// ----------------------------------------------------------------------------
// SCNN: 6 layers of (sconv -> SHT nonlinearity), B=50000, 45 coeffs, 90 dirs.
// Fully fused per-layer kernel: sconv + (isft -> relu -> sft) in one CTA pass.
// FP32 throughout (FFMA-bound). Ping-pong through __device__ scratch.
// ----------------------------------------------------------------------------

#define NB_TOTAL 50000
#define NC 45          // coefficients
#define ND 90          // directions
#define NDP 96         // padded directions (stage-1 N dim)
#define NKP 48         // padded coeffs (stage-2 N dim)
#define SIGSTR 90      // sig row stride in smem
#define NTHREADS 256

// Ping-pong buffers (allocation-free scratch). A holds up to 64 ch, B up to 32.
__device__ float g_bufA[(size_t)NB_TOTAL * 64 * NC];
__device__ float g_bufB[(size_t)NB_TOTAL * 32 * NC];

// degree group of coefficient k (l = 2g): contiguous runs of size 1,5,9,13,17
__host__ __device__ __forceinline__ constexpr int ggrp(int k) {
    return (k < 1) ? 0 : (k < 6) ? 1 : (k < 15) ? 2 : (k < 28) ? 3 : 4;
}

// scale[k] = sqrt(pi / (2l+1)), l = 2*ggrp(k)
__device__ __forceinline__ float scl_of(int k) {
    const int g = ggrp(k);
    return g == 0 ? 1.77245385090552f
         : g == 1 ? 0.79266545952121f
         : g == 2 ? 0.59081795030184f
         : g == 3 ? 0.49159027f
         :          0.42988321f;
}

// sconv over a k-range [K0, K0+KN): one thread computes one output row r for
// those k. Fully unrolled so ggrp(k)/scl_of(k) fold to constants and the
// 5-entry weight cache stays in registers.
template <int K0, int KN, int CIN, int XSTR, int MOUT>
__device__ __forceinline__ void sconv_part(const float* __restrict__ xb,
                                           const float* __restrict__ wb,
                                           float* __restrict__ yout) {
    float acc[KN];
#pragma unroll
    for (int kk = 0; kk < KN; kk++) acc[kk] = 0.f;
    for (int c = 0; c < CIN; c++) {
        float wv[5];
#pragma unroll
        for (int g = 0; g < 5; g++) wv[g] = wb[c * 5 + g];
#pragma unroll
        for (int kk = 0; kk < KN; kk++) {
            acc[kk] = fmaf(xb[(K0 + kk) * XSTR + c], wv[ggrp(K0 + kk)], acc[kk]);
        }
    }
#pragma unroll
    for (int kk = 0; kk < KN; kk++) {
        yout[(K0 + kk) * MOUT] = acc[kk] * scl_of(K0 + kk);
    }
}

template <int CIN, int COUT, int TB>
__global__ void __launch_bounds__(NTHREADS)
scnn_layer(const float* __restrict__ in, const float* __restrict__ w,
           const float* __restrict__ sft, const float* __restrict__ isft,
           float* __restrict__ out) {
    constexpr int MIN_ = TB * CIN;
    constexpr int MOUT = TB * COUT;          // rows produced by this CTA
    constexpr int XSTR = MIN_ + 1;           // odd stride: conflict-free x writes
    constexpr int WSTR = CIN * 5 + 1;        // odd stride: conflict-free w reads
    constexpr int R1T  = MOUT / 16;          // stage-1 rows per thread
    constexpr int R2T  = MOUT / 16;          // stage-2 rows per thread
    static_assert(MOUT % 16 == 0, "MOUT must be multiple of 16");
    static_assert(2 * MOUT <= NTHREADS, "sconv mapping needs 2*MOUT <= threads");

    extern __shared__ float sm[];
    float* s_x    = sm;                      // [NC][XSTR]          x as [k][m]
    float* s_w    = s_x    + NC * XSTR;      // [COUT][WSTR]
    float* s_isft = s_w    + COUT * WSTR;    // [NC][NDP]           isft^T [k][p]
    float* s_sftP = s_isft + NC * NDP;       // [ND][NKP]           sft^T  [p][k]
    float* s_y    = s_sftP + ND * NKP;       // [NC][MOUT]          y as [k][r]
    float* s_sig  = s_y    + NC * MOUT;      // [MOUT][SIGSTR]      sig [r][p]

    const int tid = threadIdx.x;
    const size_t base_in  = (size_t)blockIdx.x * (TB * CIN * NC);
    const size_t base_out = (size_t)blockIdx.x * (TB * COUT * NC);

    // ---- cooperative loads (coalesced global, conflict-free smem) ----------
    for (int i = tid; i < TB * CIN * NC; i += NTHREADS) {
        int m = i / NC, k = i - m * NC;
        s_x[k * XSTR + m] = in[base_in + i];
    }
    for (int i = tid; i < COUT * CIN * 5; i += NTHREADS) {
        int o = i / (CIN * 5);
        s_w[o * WSTR + (i - o * (CIN * 5))] = w[i];
    }
    for (int i = tid; i < ND * NC; i += NTHREADS) {   // isft is [p][k] in gmem
        int p = i / NC, k = i - p * NC;
        s_isft[k * NDP + p] = isft[i];
    }
    for (int i = tid; i < NC * (NDP - ND); i += NTHREADS) {  // zero p-pads
        int k = i / (NDP - ND), j = i - k * (NDP - ND);
        s_isft[k * NDP + ND + j] = 0.f;
    }
    for (int i = tid; i < NC * ND; i += NTHREADS) {   // sft is [k][p] in gmem
        int k = i / ND, p = i - k * ND;
        s_sftP[p * NKP + k] = sft[i];
    }
    for (int i = tid; i < ND * (NKP - NC); i += NTHREADS) {  // zero k-pads
        int p = i / (NKP - NC), j = i - p * (NKP - NC);
        s_sftP[p * NKP + NC + j] = 0.f;
    }
    __syncthreads();

    // ---- sconv: s_y[k][r] = scale[k] * sum_c x[t,c,k] * w[o,c,g(k)] --------
    // thread -> (row r, k-half). Warp-uniform half selection.
    if (tid < 2 * MOUT) {
        const int r  = (tid < MOUT) ? tid : tid - MOUT;
        const int kh = (tid < MOUT) ? 0 : 1;
        const int t = r / COUT;
        const int o = r - t * COUT;
        const float* xb = s_x + t * CIN;
        const float* wb = s_w + o * WSTR;
        if (kh == 0) sconv_part< 0, 23, CIN, XSTR, MOUT>(xb, wb, s_y + r);
        else         sconv_part<23, 22, CIN, XSTR, MOUT>(xb, wb, s_y + r);
    }
    __syncthreads();

    // ---- stage 1: sig[r][p] = relu( sum_k y[k][r] * isftT[k][p] ) ----------
    // thread (ty,tx): R1T rows x 6 p-values (p = tx + 16j). 14 LDS / 48 FMA.
    {
        const int ty = tid >> 4, tx = tid & 15;
        float acc[R1T][6];
#pragma unroll
        for (int i = 0; i < R1T; i++)
#pragma unroll
            for (int j = 0; j < 6; j++) acc[i][j] = 0.f;

        const float* yb = s_y + ty * R1T;
        const float* fb = s_isft + tx;
        for (int k = 0; k < NC; k++) {
            float yv[R1T], fv[6];
#pragma unroll
            for (int i = 0; i < R1T; i++) yv[i] = yb[k * MOUT + i];
#pragma unroll
            for (int j = 0; j < 6; j++)  fv[j] = fb[k * NDP + 16 * j];
#pragma unroll
            for (int i = 0; i < R1T; i++)
#pragma unroll
                for (int j = 0; j < 6; j++)
                    acc[i][j] = fmaf(yv[i], fv[j], acc[i][j]);
        }
#pragma unroll
        for (int i = 0; i < R1T; i++) {
            float* srow = s_sig + (size_t)(ty * R1T + i) * SIGSTR;
#pragma unroll
            for (int j = 0; j < 6; j++) {
                int p = tx + 16 * j;
                if (p < ND) srow[p] = fmaxf(acc[i][j], 0.f);
            }
        }
    }
    __syncthreads();

    // ---- stage 2: out[r][k] = sum_p sftT[p][k] * sig[r][p] -----------------
    // thread (ty,tx): R2T rows x 3 k-values (k = 3*tx + j). 11 LDS / 24 FMA.
    {
        const int ty = tid >> 4, tx = tid & 15;
        float acc[R2T][3];
#pragma unroll
        for (int i = 0; i < R2T; i++)
#pragma unroll
            for (int j = 0; j < 3; j++) acc[i][j] = 0.f;

        const float* sb = s_sig + (size_t)(ty * R2T) * SIGSTR;
        const float* fb = s_sftP + tx * 3;
        for (int p = 0; p < ND; p++) {
            float sv[R2T], fv[3];
#pragma unroll
            for (int i = 0; i < R2T; i++) sv[i] = sb[(size_t)i * SIGSTR + p];
#pragma unroll
            for (int j = 0; j < 3; j++)  fv[j] = fb[p * NKP + j];
#pragma unroll
            for (int i = 0; i < R2T; i++)
#pragma unroll
                for (int j = 0; j < 3; j++)
                    acc[i][j] = fmaf(sv[i], fv[j], acc[i][j]);
        }
#pragma unroll
        for (int i = 0; i < R2T; i++) {
            int r = ty * R2T + i;
#pragma unroll
            for (int j = 0; j < 3; j++) {
                int k = tx * 3 + j;
                if (k < NC) out[base_out + (size_t)r * NC + k] = acc[i][j];
            }
        }
    }
}

// smem size (bytes) for a given layer config
#define SMEMSZ(CIN, COUT, TB)                                                  \
    (int)(((NC * ((TB) * (CIN) + 1)) + (COUT) * ((CIN) * 5 + 1) +              \
           NC * NDP + ND * NKP + NC * (TB) * (COUT) +                          \
           (TB) * (COUT) * SIGSTR) * sizeof(float))

extern "C" void kernel_launch(void* const* d_in, const int* in_sizes, int n_in,
                              void* d_out, int out_size) {
    (void)in_sizes; (void)n_in; (void)out_size;

    const float* x    = (const float*)d_in[0];
    const float* sft  = (const float*)d_in[1];
    const float* isft = (const float*)d_in[2];
    const float* w1   = (const float*)d_in[3];
    const float* w2   = (const float*)d_in[4];
    const float* w3   = (const float*)d_in[5];
    const float* w4   = (const float*)d_in[6];
    const float* w5   = (const float*)d_in[7];
    const float* w6   = (const float*)d_in[8];
    float* out = (float*)d_out;

    float *bufA = nullptr, *bufB = nullptr;
    cudaGetSymbolAddress((void**)&bufA, g_bufA);
    cudaGetSymbolAddress((void**)&bufB, g_bufB);

    // opt-in to large dynamic smem (idempotent; capture-safe, not a stream op)
    cudaFuncSetAttribute((const void*)scnn_layer<4, 16, 8>,
                         cudaFuncAttributeMaxDynamicSharedMemorySize, SMEMSZ(4, 16, 8));
    cudaFuncSetAttribute((const void*)scnn_layer<16, 32, 4>,
                         cudaFuncAttributeMaxDynamicSharedMemorySize, SMEMSZ(16, 32, 4));
    cudaFuncSetAttribute((const void*)scnn_layer<32, 64, 2>,
                         cudaFuncAttributeMaxDynamicSharedMemorySize, SMEMSZ(32, 64, 2));
    cudaFuncSetAttribute((const void*)scnn_layer<64, 32, 4>,
                         cudaFuncAttributeMaxDynamicSharedMemorySize, SMEMSZ(64, 32, 4));
    cudaFuncSetAttribute((const void*)scnn_layer<32, 16, 8>,
                         cudaFuncAttributeMaxDynamicSharedMemorySize, SMEMSZ(32, 16, 8));
    cudaFuncSetAttribute((const void*)scnn_layer<16, 4, 16>,
                         cudaFuncAttributeMaxDynamicSharedMemorySize, SMEMSZ(16, 4, 16));

    // L1: x(4ch) -> A(16ch)
    scnn_layer<4, 16, 8><<<NB_TOTAL / 8, NTHREADS, SMEMSZ(4, 16, 8)>>>(
        x, w1, sft, isft, bufA);
    // L2: A(16) -> B(32)
    scnn_layer<16, 32, 4><<<NB_TOTAL / 4, NTHREADS, SMEMSZ(16, 32, 4)>>>(
        bufA, w2, sft, isft, bufB);
    // L3: B(32) -> A(64)
    scnn_layer<32, 64, 2><<<NB_TOTAL / 2, NTHREADS, SMEMSZ(32, 64, 2)>>>(
        bufB, w3, sft, isft, bufA);
    // L4: A(64) -> B(32)
    scnn_layer<64, 32, 4><<<NB_TOTAL / 4, NTHREADS, SMEMSZ(64, 32, 4)>>>(
        bufA, w4, sft, isft, bufB);
    // L5: B(32) -> A(16)
    scnn_layer<32, 16, 8><<<NB_TOTAL / 8, NTHREADS, SMEMSZ(32, 16, 8)>>>(
        bufB, w5, sft, isft, bufA);
    // L6: A(16) -> out(4)
    scnn_layer<16, 4, 16><<<NB_TOTAL / 16, NTHREADS, SMEMSZ(16, 4, 16)>>>(
        bufA, w6, sft, isft, out);
}

// round 3
// speedup vs baseline: 1.4097x; 1.4097x over previous
#include <cuda_runtime.h>
#include <cstdint>
#include <cstddef>

// ----------------------------------------------------------------------------
// SCNN: 6 layers of (sconv -> SHT nonlinearity), B=50000, 45 coeffs, 90 dirs.
// Per-layer fused kernel. FP32, FFMA-bound. Key R3 changes:
//  - smem <= ~109KB/CTA -> 2 CTAs/SM (sig aliases x+w regions)
//  - float4 LDS in sconv / stage1 / stage2 to cut L1 wavefronts
//  - 4-way k-split sconv when MOUT=64 (all 256 threads active)
// ----------------------------------------------------------------------------

#define NB_TOTAL 50000
#define NC 45          // coefficients
#define ND 90          // directions
#define NDP 96         // padded directions (stage-1 N dim)
#define NKP 48         // padded coeffs (stage-2 N dim)
#define SIGSTR 92      // sig row stride (pad 90->92, mult of 4)
#define NTHREADS 256

// Ping-pong buffers (allocation-free scratch).
__device__ float g_bufA[(size_t)NB_TOTAL * 64 * NC];
__device__ float g_bufB[(size_t)NB_TOTAL * 32 * NC];

// degree group of coefficient k (l = 2g): contiguous runs of size 1,5,9,13,17
__host__ __device__ __forceinline__ constexpr int ggrp(int k) {
    return (k < 1) ? 0 : (k < 6) ? 1 : (k < 15) ? 2 : (k < 28) ? 3 : 4;
}

// scale[k] = sqrt(pi / (2l+1)), l = 2*ggrp(k)  (verified: rel_err 2.4e-7)
__device__ __forceinline__ float scl_of(int k) {
    const int g = ggrp(k);
    return g == 0 ? 1.77245385090552f
         : g == 1 ? 0.79266545952121f
         : g == 2 ? 0.59081795030184f
         : g == 3 ? 0.49159027f
         :          0.42988321f;
}

// sconv over k-range [K0, K0+KN): one thread, one output row r.
// c-blocked (CB=4): weights cached in registers, x loaded as float4
// (warp-broadcast). ggrp/scl fold to compile-time constants.
template <int K0, int KN, int CIN, int XSTR, int MOUT>
__device__ __forceinline__ void sconv_part(const float* __restrict__ xb,
                                           const float* __restrict__ wb,
                                           float* __restrict__ yout) {
    float acc[KN];
#pragma unroll
    for (int kk = 0; kk < KN; kk++) acc[kk] = 0.f;

#pragma unroll 1
    for (int cb = 0; cb < CIN; cb += 4) {
        float wv[4][5];
#pragma unroll
        for (int cc = 0; cc < 4; cc++)
#pragma unroll
            for (int g = 0; g < 5; g++) wv[cc][g] = wb[(cb + cc) * 5 + g];
#pragma unroll
        for (int kk = 0; kk < KN; kk++) {
            const float4 xv =
                *reinterpret_cast<const float4*>(xb + (K0 + kk) * XSTR + cb);
            constexpr int dummy = 0; (void)dummy;
            const int g = ggrp(K0 + kk);   // constant after unroll
            acc[kk] = fmaf(xv.x, wv[0][g], acc[kk]);
            acc[kk] = fmaf(xv.y, wv[1][g], acc[kk]);
            acc[kk] = fmaf(xv.z, wv[2][g], acc[kk]);
            acc[kk] = fmaf(xv.w, wv[3][g], acc[kk]);
        }
    }
#pragma unroll
    for (int kk = 0; kk < KN; kk++)
        yout[(K0 + kk) * MOUT] = acc[kk] * scl_of(K0 + kk);
}

template <int CIN, int COUT, int TB>
__global__ void __launch_bounds__(NTHREADS, 2)
scnn_layer(const float* __restrict__ in, const float* __restrict__ w,
           const float* __restrict__ sft, const float* __restrict__ isft,
           float* __restrict__ out) {
    constexpr int MIN_ = TB * CIN;
    constexpr int MOUT = TB * COUT;          // rows produced by this CTA
    constexpr int XSTR = MIN_ + 4;           // mult-of-4 (float4), not mult-32
    constexpr int WSTR = CIN * 5 + 1;        // odd: conflict-free w reads
    constexpr int KSPLIT = NTHREADS / MOUT;  // 2 (MOUT=128) or 4 (MOUT=64)
    constexpr int R1T = MOUT / 16;           // rows/thread, stage 1
    constexpr int R2T = MOUT / 16;           // rows/thread, stage 2
    static_assert(MOUT == 64 || MOUT == 128, "tile");
    static_assert(KSPLIT * MOUT == NTHREADS, "sconv mapping");
    static_assert(CIN % 4 == 0, "c-block");

    extern __shared__ float sm[];
    float* s_isft = sm;                        // [NC][NDP]    isft^T [k][p]
    float* s_sftP = s_isft + NC * NDP;         // [SIGSTR][NKP] sft^T [p][k]
    float* s_y    = s_sftP + SIGSTR * NKP;     // [NC][MOUT]   y as [k][r]
    float* s_un   = s_y + NC * MOUT;           // union region:
    float* s_x    = s_un;                      //   [NC][XSTR]  x as [k][m]
    float* s_w    = s_un + NC * XSTR;          //   [COUT][WSTR]
    float* s_sig  = s_un;                      //   [MOUT][SIGSTR] (aliases x,w)

    const int tid = threadIdx.x;
    const size_t base_in  = (size_t)blockIdx.x * (TB * CIN * NC);
    const size_t base_out = (size_t)blockIdx.x * (TB * COUT * NC);

    // ---- cooperative loads ------------------------------------------------
    for (int i = tid; i < MIN_ * NC; i += NTHREADS) {
        int m = i / NC, k = i - m * NC;
        s_x[k * XSTR + m] = in[base_in + i];
    }
    for (int i = tid; i < COUT * CIN * 5; i += NTHREADS) {
        int o = i / (CIN * 5);
        s_w[o * WSTR + (i - o * (CIN * 5))] = w[i];
    }
    for (int i = tid; i < ND * NC; i += NTHREADS) {   // isft gmem = [p][k]
        int p = i / NC, k = i - p * NC;
        s_isft[k * NDP + p] = isft[i];
    }
    for (int i = tid; i < NC * (NDP - ND); i += NTHREADS) {  // p-pads
        int k = i / (NDP - ND), j = i - k * (NDP - ND);
        s_isft[k * NDP + ND + j] = 0.f;
    }
    for (int i = tid; i < NC * ND; i += NTHREADS) {   // sft gmem = [k][p]
        int k = i / ND, p = i - k * ND;
        s_sftP[p * NKP + k] = sft[i];
    }
    // sftP pads: cols 45..47 for all 92 rows (276) + rows 90..91 cols 0..44 (90)
    for (int i = tid; i < 276 + 2 * NC; i += NTHREADS) {
        int p, k;
        if (i < 276) { p = i / 3; k = NC + (i - p * 3); }
        else         { int j = i - 276; p = ND + j / NC; k = j - (j / NC) * NC; }
        s_sftP[p * NKP + k] = 0.f;
    }
    __syncthreads();

    // ---- sconv: s_y[k][r] = scale[k] * sum_c x[t,c,k] * w[o,c,g(k)] --------
    {
        const int r   = tid & (MOUT - 1);
        const int seg = tid / MOUT;          // warp-uniform (MOUT mult of 32)
        const int t = r / COUT;
        const int o = r & (COUT - 1);
        const float* xb = s_x + t * CIN;
        const float* wb = s_w + o * WSTR;
        float* yo = s_y + r;
        if constexpr (KSPLIT == 2) {
            if (seg == 0) sconv_part< 0, 23, CIN, XSTR, MOUT>(xb, wb, yo);
            else          sconv_part<23, 22, CIN, XSTR, MOUT>(xb, wb, yo);
        } else {
            if      (seg == 0) sconv_part< 0, 12, CIN, XSTR, MOUT>(xb, wb, yo);
            else if (seg == 1) sconv_part<12, 11, CIN, XSTR, MOUT>(xb, wb, yo);
            else if (seg == 2) sconv_part<23, 11, CIN, XSTR, MOUT>(xb, wb, yo);
            else               sconv_part<34, 11, CIN, XSTR, MOUT>(xb, wb, yo);
        }
    }
    __syncthreads();

    // ---- stage 1: sig[r][p] = relu( sum_k y[k][r] * isftT[k][p] ) ----------
    // thread (ty,tx): R1T rows (float4 y loads) x 6 p-values.
    {
        const int ty = tid >> 4, tx = tid & 15;
        float acc[R1T][6];
#pragma unroll
        for (int i = 0; i < R1T; i++)
#pragma unroll
            for (int j = 0; j < 6; j++) acc[i][j] = 0.f;

        const float4* yb4 = reinterpret_cast<const float4*>(s_y + ty * R1T);
        const float* fb = s_isft + tx;
        for (int k = 0; k < NC; k++) {
            float yv[R1T];
#pragma unroll
            for (int v = 0; v < R1T / 4; v++) {
                float4 t4 = yb4[k * (MOUT / 4) + v];
                yv[4 * v + 0] = t4.x; yv[4 * v + 1] = t4.y;
                yv[4 * v + 2] = t4.z; yv[4 * v + 3] = t4.w;
            }
            float fv[6];
#pragma unroll
            for (int j = 0; j < 6; j++) fv[j] = fb[k * NDP + 16 * j];
#pragma unroll
            for (int i = 0; i < R1T; i++)
#pragma unroll
                for (int j = 0; j < 6; j++)
                    acc[i][j] = fmaf(yv[i], fv[j], acc[i][j]);
        }
#pragma unroll
        for (int i = 0; i < R1T; i++) {
            float* srow = s_sig + (ty * R1T + i) * SIGSTR;
#pragma unroll
            for (int j = 0; j < 6; j++) {
                const int p = tx + 16 * j;
                if (p < ND)          srow[p] = fmaxf(acc[i][j], 0.f);
                else if (p < SIGSTR) srow[p] = 0.f;   // zero pad cols 90..91
            }
        }
    }
    __syncthreads();

    // ---- stage 2: out[r][k] = sum_p sftT[p][k] * sig[r][p] -----------------
    // thread (ty,tx): R2T rows x 3 k, 4 p per iter with float4 sig loads.
    {
        const int ty = tid >> 4, tx = tid & 15;
        float acc[R2T][3];
#pragma unroll
        for (int i = 0; i < R2T; i++)
#pragma unroll
            for (int j = 0; j < 3; j++) acc[i][j] = 0.f;

        const float* sb = s_sig + ty * R2T * SIGSTR;
        const float* fb = s_sftP + tx * 3;
        for (int p = 0; p < SIGSTR; p += 4) {
            float sv[R2T][4];
#pragma unroll
            for (int i = 0; i < R2T; i++) {
                float4 t4 = *reinterpret_cast<const float4*>(sb + i * SIGSTR + p);
                sv[i][0] = t4.x; sv[i][1] = t4.y; sv[i][2] = t4.z; sv[i][3] = t4.w;
            }
            float fv[4][3];
#pragma unroll
            for (int pp = 0; pp < 4; pp++)
#pragma unroll
                for (int j = 0; j < 3; j++) fv[pp][j] = fb[(p + pp) * NKP + j];
#pragma unroll
            for (int i = 0; i < R2T; i++)
#pragma unroll
                for (int pp = 0; pp < 4; pp++)
#pragma unroll
                    for (int j = 0; j < 3; j++)
                        acc[i][j] = fmaf(sv[i][pp], fv[pp][j], acc[i][j]);
        }
#pragma unroll
        for (int i = 0; i < R2T; i++) {
            const int r = ty * R2T + i;
#pragma unroll
            for (int j = 0; j < 3; j++) {
                const int k = tx * 3 + j;
                if (k < NC) out[base_out + (size_t)r * NC + k] = acc[i][j];
            }
        }
    }
}

// smem floats for a layer config (must mirror kernel layout)
constexpr size_t smem_floats(int CIN, int COUT, int TB) {
    const int MIN_ = TB * CIN, MOUT = TB * COUT;
    const int XSTR = MIN_ + 4, WSTR = CIN * 5 + 1;
    const size_t fixed = (size_t)NC * NDP + (size_t)SIGSTR * NKP + (size_t)NC * MOUT;
    const size_t xw  = (size_t)NC * XSTR + (size_t)COUT * WSTR;
    const size_t sig = (size_t)MOUT * SIGSTR;
    return fixed + (xw > sig ? xw : sig);
}
#define SMEMB(CIN, COUT, TB) ((int)(smem_floats(CIN, COUT, TB) * sizeof(float)))

extern "C" void kernel_launch(void* const* d_in, const int* in_sizes, int n_in,
                              void* d_out, int out_size) {
    (void)in_sizes; (void)n_in; (void)out_size;

    const float* x    = (const float*)d_in[0];
    const float* sft  = (const float*)d_in[1];
    const float* isft = (const float*)d_in[2];
    const float* w1   = (const float*)d_in[3];
    const float* w2   = (const float*)d_in[4];
    const float* w3   = (const float*)d_in[5];
    const float* w4   = (const float*)d_in[6];
    const float* w5   = (const float*)d_in[7];
    const float* w6   = (const float*)d_in[8];
    float* out = (float*)d_out;

    float *bufA = nullptr, *bufB = nullptr;
    cudaGetSymbolAddress((void**)&bufA, g_bufA);
    cudaGetSymbolAddress((void**)&bufB, g_bufB);

    cudaFuncSetAttribute((const void*)scnn_layer<4, 16, 8>,
                         cudaFuncAttributeMaxDynamicSharedMemorySize, SMEMB(4, 16, 8));
    cudaFuncSetAttribute((const void*)scnn_layer<16, 32, 4>,
                         cudaFuncAttributeMaxDynamicSharedMemorySize, SMEMB(16, 32, 4));
    cudaFuncSetAttribute((const void*)scnn_layer<32, 64, 2>,
                         cudaFuncAttributeMaxDynamicSharedMemorySize, SMEMB(32, 64, 2));
    cudaFuncSetAttribute((const void*)scnn_layer<64, 32, 2>,
                         cudaFuncAttributeMaxDynamicSharedMemorySize, SMEMB(64, 32, 2));
    cudaFuncSetAttribute((const void*)scnn_layer<32, 16, 4>,
                         cudaFuncAttributeMaxDynamicSharedMemorySize, SMEMB(32, 16, 4));
    cudaFuncSetAttribute((const void*)scnn_layer<16, 4, 16>,
                         cudaFuncAttributeMaxDynamicSharedMemorySize, SMEMB(16, 4, 16));

    // L1: x(4ch) -> A(16ch), MOUT=128
    scnn_layer<4, 16, 8><<<NB_TOTAL / 8, NTHREADS, SMEMB(4, 16, 8)>>>(
        x, w1, sft, isft, bufA);
    // L2: A(16) -> B(32), MOUT=128
    scnn_layer<16, 32, 4><<<NB_TOTAL / 4, NTHREADS, SMEMB(16, 32, 4)>>>(
        bufA, w2, sft, isft, bufB);
    // L3: B(32) -> A(64), MOUT=128
    scnn_layer<32, 64, 2><<<NB_TOTAL / 2, NTHREADS, SMEMB(32, 64, 2)>>>(
        bufB, w3, sft, isft, bufA);
    // L4: A(64) -> B(32), MOUT=64
    scnn_layer<64, 32, 2><<<NB_TOTAL / 2, NTHREADS, SMEMB(64, 32, 2)>>>(
        bufA, w4, sft, isft, bufB);
    // L5: B(32) -> A(16), MOUT=64
    scnn_layer<32, 16, 4><<<NB_TOTAL / 4, NTHREADS, SMEMB(32, 16, 4)>>>(
        bufB, w5, sft, isft, bufA);
    // L6: A(16) -> out(4), MOUT=64
    scnn_layer<16, 4, 16><<<NB_TOTAL / 16, NTHREADS, SMEMB(16, 4, 16)>>>(
        bufA, w6, sft, isft, out);
}

// round 5
// speedup vs baseline: 1.6982x; 1.2046x over previous
#include <cuda_runtime.h>
#include <cuda_bf16.h>
#include <cstdint>
#include <cstddef>

// ----------------------------------------------------------------------------
// SCNN via warp-level HMMA (mma.sync bf16, fp32 accum) — compiles for plain
// sm_103 (no tcgen05). sconv in FFMA with bf16 hi/lo split epilogue; both SHT
// GEMMs per layer on tensor cores with 3 split products (hihi+hilo+lohi).
// 512 threads/CTA, 1 CTA/SM, all operands staged in smem for ldmatrix.
// ----------------------------------------------------------------------------

#define NB_TOTAL 50000
#define NC 45
#define ND 90
#define NT 512

#define YSTR   56   // Y tile row stride (bf16 elems): 112B -> conflict-free
#define B1STR  56   // B1 [n=96][k=48]
#define B2STR 104   // B2 [n=48][k=96]: 208B -> conflict-free
#define SIGSTR 104  // sig [m=128][p=96]
#define STGSTR 50   // fp32 staging row stride

__device__ float g_bufA[(size_t)NB_TOTAL * 64 * NC];
__device__ float g_bufB[(size_t)NB_TOTAL * 32 * NC];
// Packed bf16 hi/lo B matrices, built once: B1=[n=96][k=48], B2=[n=48][k=96]
__device__ __nv_bfloat16 g_B1h[96 * 48], g_B1l[96 * 48];
__device__ __nv_bfloat16 g_B2h[48 * 96], g_B2l[48 * 96];

// ---------------- smem layout (bytes) ---------------------------------------
#define OFF_B1H 0
#define OFF_B1L 10752          /* 96*56*2 */
#define OFF_B2H 21504
#define OFF_B2L 31488          /* +48*104*2 */
#define OFF_YH  41472
#define OFF_YL  55808          /* +128*56*2 */
#define OFF_SGH 70144
#define OFF_SGL 96768          /* +128*104*2 */
#define OFF_U   123392         /* union: x (sconv) | fp32 staging (epilogue2) */

__host__ __device__ constexpr int align16(int x) { return (x + 15) & ~15; }
__host__ __device__ constexpr int xbytes_c(int CIN, int TB) {
    return NC * (TB * CIN + 4) * 4;
}
__host__ __device__ constexpr int ubytes_c(int CIN, int TB) {
    return align16(xbytes_c(CIN, TB) > 128 * STGSTR * 4 ? xbytes_c(CIN, TB)
                                                        : 128 * STGSTR * 4);
}
__host__ __device__ constexpr int off_w_c(int CIN, int TB) {
    return OFF_U + ubytes_c(CIN, TB);
}
__host__ __device__ constexpr int smem_total_c(int CIN, int COUT, int TB) {
    return off_w_c(CIN, TB) + COUT * (CIN * 5 + 1) * 4;
}

// ---------------- PTX helpers ----------------------------------------------
__device__ __forceinline__ uint32_t smem_u32(const void* p) {
    uint32_t a;
    asm("{ .reg .u64 t; cvta.to.shared.u64 t, %1; cvt.u32.u64 %0, t; }"
        : "=r"(a) : "l"(p));
    return a;
}
__device__ __forceinline__ void ldsm_x4(uint32_t* r, uint32_t addr) {
    asm volatile("ldmatrix.sync.aligned.m8n8.x4.shared.b16 {%0,%1,%2,%3}, [%4];"
                 : "=r"(r[0]), "=r"(r[1]), "=r"(r[2]), "=r"(r[3]) : "r"(addr));
}
__device__ __forceinline__ void ldsm_x2(uint32_t* r, uint32_t addr) {
    asm volatile("ldmatrix.sync.aligned.m8n8.x2.shared.b16 {%0,%1}, [%2];"
                 : "=r"(r[0]), "=r"(r[1]) : "r"(addr));
}
__device__ __forceinline__ void mma_bf16(float* c, const uint32_t* a,
                                         uint32_t b0, uint32_t b1) {
    asm volatile(
        "mma.sync.aligned.m16n8k16.row.col.f32.bf16.bf16.f32 "
        "{%0,%1,%2,%3}, {%4,%5,%6,%7}, {%8,%9}, {%0,%1,%2,%3};"
        : "+f"(c[0]), "+f"(c[1]), "+f"(c[2]), "+f"(c[3])
        : "r"(a[0]), "r"(a[1]), "r"(a[2]), "r"(a[3]), "r"(b0), "r"(b1));
}
__device__ __forceinline__ uint32_t pack2bf(__nv_bfloat16 a, __nv_bfloat16 b) {
    return (uint32_t)__bfloat16_as_ushort(a) |
           ((uint32_t)__bfloat16_as_ushort(b) << 16);
}

// ---------------- problem constants -----------------------------------------
__host__ __device__ __forceinline__ constexpr int ggrp(int k) {
    return (k < 1) ? 0 : (k < 6) ? 1 : (k < 15) ? 2 : (k < 28) ? 3 : 4;
}
__device__ __forceinline__ float scl_of(int k) {
    const int g = ggrp(k);
    return g == 0 ? 1.77245385090552f
         : g == 1 ? 0.79266545952121f
         : g == 2 ? 0.59081795030184f
         : g == 3 ? 0.49159027f
         :          0.42988321f;
}

// ---------------- setup: pre-split B matrices to bf16 hi/lo -----------------
__global__ void build_B(const float* __restrict__ sft,
                        const float* __restrict__ isft) {
    const int tid = threadIdx.x;
    for (int i = tid; i < 96 * 48; i += NT) {      // B1[n=p(96)][k(48)]
        int n = i / 48, k = i - n * 48;
        float v = (n < ND && k < NC) ? isft[n * NC + k] : 0.f;
        __nv_bfloat16 hi = __float2bfloat16(v);
        g_B1h[i] = hi;
        g_B1l[i] = __float2bfloat16(v - __bfloat162float(hi));
    }
    for (int i = tid; i < 48 * 96; i += NT) {      // B2[n=k(48)][k=p(96)]
        int n = i / 96, p = i - n * 96;
        float v = (n < NC && p < ND) ? sft[n * ND + p] : 0.f;
        __nv_bfloat16 hi = __float2bfloat16(v);
        g_B2h[i] = hi;
        g_B2l[i] = __float2bfloat16(v - __bfloat162float(hi));
    }
}

// sconv over k in [K0,K0+KN): one thread, one row r; outputs bf16 hi/lo pairs.
template <int K0, int KN, int CIN, int XSTR>
__device__ __forceinline__ void sconv_seg(const float* __restrict__ xb,
                                          const float* __restrict__ wb,
                                          __nv_bfloat16* __restrict__ yh,
                                          __nv_bfloat16* __restrict__ yl,
                                          int r) {
    float acc[KN];
#pragma unroll
    for (int kk = 0; kk < KN; kk++) acc[kk] = 0.f;
#pragma unroll 1
    for (int cb = 0; cb < CIN; cb += 4) {
        float wv[4][5];
#pragma unroll
        for (int cc = 0; cc < 4; cc++)
#pragma unroll
            for (int g = 0; g < 5; g++) wv[cc][g] = wb[(cb + cc) * 5 + g];
#pragma unroll
        for (int kk = 0; kk < KN; kk++) {
            const float4 xv =
                *reinterpret_cast<const float4*>(xb + (K0 + kk) * XSTR + cb);
            const int g = ggrp(K0 + kk);
            acc[kk] = fmaf(xv.x, wv[0][g], acc[kk]);
            acc[kk] = fmaf(xv.y, wv[1][g], acc[kk]);
            acc[kk] = fmaf(xv.z, wv[2][g], acc[kk]);
            acc[kk] = fmaf(xv.w, wv[3][g], acc[kk]);
        }
    }
#pragma unroll
    for (int kk = 0; kk + 1 < KN; kk += 2) {
        const float v0 = acc[kk] * scl_of(K0 + kk);
        const float v1 = acc[kk + 1] * scl_of(K0 + kk + 1);
        const __nv_bfloat16 h0 = __float2bfloat16(v0);
        const __nv_bfloat16 h1 = __float2bfloat16(v1);
        const __nv_bfloat16 l0 = __float2bfloat16(v0 - __bfloat162float(h0));
        const __nv_bfloat16 l1 = __float2bfloat16(v1 - __bfloat162float(h1));
        *(uint32_t*)(yh + r * YSTR + K0 + kk) = pack2bf(h0, h1);
        *(uint32_t*)(yl + r * YSTR + K0 + kk) = pack2bf(l0, l1);
    }
    if constexpr (KN & 1) {
        const int k = K0 + KN - 1;
        const float v = acc[KN - 1] * scl_of(k);
        const __nv_bfloat16 h = __float2bfloat16(v);
        yh[r * YSTR + k] = h;
        yl[r * YSTR + k] = __float2bfloat16(v - __bfloat162float(h));
    }
}

// ---------------- per-layer kernel ------------------------------------------
template <int CIN, int COUT, int TB>
__global__ void __launch_bounds__(NT, 1)
scnn_layer(const float* __restrict__ in, const float* __restrict__ w,
           float* __restrict__ out) {
    static_assert(TB * COUT == 128, "MOUT must be 128");
    static_assert(CIN % 4 == 0, "c-block");
    constexpr int MIN_ = TB * CIN;
    constexpr int XSTR = MIN_ + 4;
    constexpr int WSTR = CIN * 5 + 1;
    constexpr int OFF_W = off_w_c(CIN, TB);

    extern __shared__ char smc[];
    const uint32_t sb = smem_u32(smc);
    const int tid = threadIdx.x, wid = tid >> 5, lane = tid & 31;

    const size_t base_in  = (size_t)blockIdx.x * (TB * CIN * NC);
    const size_t base_out = (size_t)blockIdx.x * (TB * COUT * NC);

    __nv_bfloat16* Yh  = (__nv_bfloat16*)(smc + OFF_YH);
    __nv_bfloat16* Yl  = (__nv_bfloat16*)(smc + OFF_YL);
    __nv_bfloat16* SGh = (__nv_bfloat16*)(smc + OFF_SGH);
    __nv_bfloat16* SGl = (__nv_bfloat16*)(smc + OFF_SGL);
    float* s_x = (float*)(smc + OFF_U);
    float* s_w = (float*)(smc + OFF_W);
    float* s_stg = (float*)(smc + OFF_U);          // aliases x (disjoint life)

    // ---- phase 0: zero Y pads, copy B tiles, load x & w --------------------
    for (int i = tid; i < (OFF_SGH - OFF_YH) / 4; i += NT)
        ((uint32_t*)(smc + OFF_YH))[i] = 0;        // zero Yh+Yl (covers k pads)
    {
        const uint32_t* s1h = (const uint32_t*)g_B1h;
        const uint32_t* s1l = (const uint32_t*)g_B1l;
        uint32_t* d1h = (uint32_t*)(smc + OFF_B1H);
        uint32_t* d1l = (uint32_t*)(smc + OFF_B1L);
        for (int i = tid; i < 96 * 24; i += NT) {  // [n][k] pairs
            int n = i / 24, kk = i - n * 24;
            d1h[(n * B1STR) / 2 + kk] = s1h[i];
            d1l[(n * B1STR) / 2 + kk] = s1l[i];
        }
        const uint32_t* s2h = (const uint32_t*)g_B2h;
        const uint32_t* s2l = (const uint32_t*)g_B2l;
        uint32_t* d2h = (uint32_t*)(smc + OFF_B2H);
        uint32_t* d2l = (uint32_t*)(smc + OFF_B2L);
        for (int i = tid; i < 48 * 48; i += NT) {
            int n = i / 48, kk = i - n * 48;
            d2h[(n * B2STR) / 2 + kk] = s2h[i];
            d2l[(n * B2STR) / 2 + kk] = s2l[i];
        }
    }
    for (int i = tid; i < MIN_ * NC; i += NT) {
        int m = i / NC, k = i - m * NC;
        int b = blockIdx.x * TB + m / CIN;
        s_x[k * XSTR + m] = (b < NB_TOTAL) ? in[base_in + i] : 0.f;
    }
    for (int i = tid; i < COUT * CIN * 5; i += NT) {
        int o = i / (CIN * 5);
        s_w[o * WSTR + (i - o * (CIN * 5))] = w[i];
    }
    __syncthreads();

    // ---- phase 1: sconv -> Y (bf16 hi/lo) ----------------------------------
    {
        const int r = tid & 127;
        const int seg = tid >> 7;                  // 4 k-segments
        const int t = r / COUT, o = r & (COUT - 1);
        const float* xb = s_x + t * CIN;
        const float* wb = s_w + o * WSTR;
        if      (seg == 0) sconv_seg< 0, 12, CIN, XSTR>(xb, wb, Yh, Yl, r);
        else if (seg == 1) sconv_seg<12, 12, CIN, XSTR>(xb, wb, Yh, Yl, r);
        else if (seg == 2) sconv_seg<24, 12, CIN, XSTR>(xb, wb, Yh, Yl, r);
        else               sconv_seg<36,  9, CIN, XSTR>(xb, wb, Yh, Yl, r);
    }
    __syncthreads();

    // ---- phase 2: GEMM1 sig[128x96] = relu(Y[128x48] * B1^T) ---------------
    {
        const int m0 = (wid >> 1) * 16;
        const int nbase = (wid & 1) * 48;
        const int g = lane >> 3, rr = lane & 7;
        float c[6][4];
#pragma unroll
        for (int i = 0; i < 6; i++)
#pragma unroll
            for (int j = 0; j < 4; j++) c[i][j] = 0.f;

#pragma unroll
        for (int ks = 0; ks < 3; ks++) {
            const int k0 = ks * 16;
            const uint32_t aoff =
                ((m0 + (g & 1) * 8 + rr) * YSTR + k0 + (g >> 1) * 8) * 2;
            uint32_t ah[4], al[4];
            ldsm_x4(ah, sb + OFF_YH + aoff);
            ldsm_x4(al, sb + OFF_YL + aoff);
#pragma unroll
            for (int ntp = 0; ntp < 3; ntp++) {
                const int n0 = nbase + ntp * 16;
                const uint32_t boff =
                    ((n0 + (g >> 1) * 8 + rr) * B1STR + k0 + (g & 1) * 8) * 2;
                uint32_t bh[4], bl[4];
                ldsm_x4(bh, sb + OFF_B1H + boff);
                ldsm_x4(bl, sb + OFF_B1L + boff);
                mma_bf16(c[2 * ntp], ah, bh[0], bh[1]);
                mma_bf16(c[2 * ntp], ah, bl[0], bl[1]);
                mma_bf16(c[2 * ntp], al, bh[0], bh[1]);
                mma_bf16(c[2 * ntp + 1], ah, bh[2], bh[3]);
                mma_bf16(c[2 * ntp + 1], ah, bl[2], bl[3]);
                mma_bf16(c[2 * ntp + 1], al, bh[2], bh[3]);
            }
        }
        // epilogue: relu, split hi/lo, packed u32 stores to sig
        const int qr = lane >> 2, qc = lane & 3;
#pragma unroll
        for (int nt = 0; nt < 6; nt++) {
            const int col = nbase + nt * 8 + 2 * qc;
#pragma unroll
            for (int half = 0; half < 2; half++) {
                const int row = m0 + qr + 8 * half;
                const float v0 = fmaxf(c[nt][2 * half], 0.f);
                const float v1 = fmaxf(c[nt][2 * half + 1], 0.f);
                const __nv_bfloat16 h0 = __float2bfloat16(v0);
                const __nv_bfloat16 h1 = __float2bfloat16(v1);
                const __nv_bfloat16 l0 =
                    __float2bfloat16(v0 - __bfloat162float(h0));
                const __nv_bfloat16 l1 =
                    __float2bfloat16(v1 - __bfloat162float(h1));
                *(uint32_t*)(SGh + row * SIGSTR + col) = pack2bf(h0, h1);
                *(uint32_t*)(SGl + row * SIGSTR + col) = pack2bf(l0, l1);
            }
        }
    }
    __syncthreads();

    // ---- phase 3: GEMM2 out[128x48] = sig[128x96] * B2^T -------------------
    {
        const int m0 = (wid >> 1) * 16;
        const int nbase = (wid & 1) * 24;
        const int g = lane >> 3, rr = lane & 7;
        float c[3][4];
#pragma unroll
        for (int i = 0; i < 3; i++)
#pragma unroll
            for (int j = 0; j < 4; j++) c[i][j] = 0.f;

#pragma unroll
        for (int ks = 0; ks < 6; ks++) {
            const int k0 = ks * 16;
            const uint32_t aoff =
                ((m0 + (g & 1) * 8 + rr) * SIGSTR + k0 + (g >> 1) * 8) * 2;
            uint32_t ah[4], al[4];
            ldsm_x4(ah, sb + OFF_SGH + aoff);
            ldsm_x4(al, sb + OFF_SGL + aoff);
            // n-tile pair {0,1}
            {
                const uint32_t boff =
                    ((nbase + (g >> 1) * 8 + rr) * B2STR + k0 + (g & 1) * 8) * 2;
                uint32_t bh[4], bl[4];
                ldsm_x4(bh, sb + OFF_B2H + boff);
                ldsm_x4(bl, sb + OFF_B2L + boff);
                mma_bf16(c[0], ah, bh[0], bh[1]);
                mma_bf16(c[0], ah, bl[0], bl[1]);
                mma_bf16(c[0], al, bh[0], bh[1]);
                mma_bf16(c[1], ah, bh[2], bh[3]);
                mma_bf16(c[1], ah, bl[2], bl[3]);
                mma_bf16(c[1], al, bh[2], bh[3]);
            }
            // n-tile 2 (x2 loads)
            {
                const uint32_t boff =
                    ((nbase + 16 + rr) * B2STR + k0 + (g & 1) * 8) * 2;
                uint32_t bh[2], bl[2];
                ldsm_x2(bh, sb + OFF_B2H + boff);
                ldsm_x2(bl, sb + OFF_B2L + boff);
                mma_bf16(c[2], ah, bh[0], bh[1]);
                mma_bf16(c[2], ah, bl[0], bl[1]);
                mma_bf16(c[2], al, bh[0], bh[1]);
            }
        }
        // epilogue: fp32 -> staging (float2 stores)
        const int qr = lane >> 2, qc = lane & 3;
#pragma unroll
        for (int nt = 0; nt < 3; nt++) {
            const int col = nbase + nt * 8 + 2 * qc;
#pragma unroll
            for (int half = 0; half < 2; half++) {
                const int row = m0 + qr + 8 * half;
                float2 v = make_float2(c[nt][2 * half], c[nt][2 * half + 1]);
                *(float2*)(s_stg + row * STGSTR + col) = v;
            }
        }
    }
    __syncthreads();

    // ---- phase 4: coalesced store to gmem ----------------------------------
    for (int i = tid; i < 128 * NC; i += NT) {
        const int r = i / NC, k = i - r * NC;
        const int b = blockIdx.x * TB + r / COUT;
        if (b < NB_TOTAL) out[base_out + i] = s_stg[r * STGSTR + k];
    }
}

// ---------------- host ------------------------------------------------------
extern "C" void kernel_launch(void* const* d_in, const int* in_sizes, int n_in,
                              void* d_out, int out_size) {
    (void)in_sizes; (void)n_in; (void)out_size;

    const float* x    = (const float*)d_in[0];
    const float* sft  = (const float*)d_in[1];
    const float* isft = (const float*)d_in[2];
    const float* w1   = (const float*)d_in[3];
    const float* w2   = (const float*)d_in[4];
    const float* w3   = (const float*)d_in[5];
    const float* w4   = (const float*)d_in[6];
    const float* w5   = (const float*)d_in[7];
    const float* w6   = (const float*)d_in[8];
    float* out = (float*)d_out;

    float *bufA = nullptr, *bufB = nullptr;
    cudaGetSymbolAddress((void**)&bufA, g_bufA);
    cudaGetSymbolAddress((void**)&bufB, g_bufB);

    cudaFuncSetAttribute((const void*)scnn_layer<4, 16, 8>,
        cudaFuncAttributeMaxDynamicSharedMemorySize, smem_total_c(4, 16, 8));
    cudaFuncSetAttribute((const void*)scnn_layer<16, 32, 4>,
        cudaFuncAttributeMaxDynamicSharedMemorySize, smem_total_c(16, 32, 4));
    cudaFuncSetAttribute((const void*)scnn_layer<32, 64, 2>,
        cudaFuncAttributeMaxDynamicSharedMemorySize, smem_total_c(32, 64, 2));
    cudaFuncSetAttribute((const void*)scnn_layer<64, 32, 4>,
        cudaFuncAttributeMaxDynamicSharedMemorySize, smem_total_c(64, 32, 4));
    cudaFuncSetAttribute((const void*)scnn_layer<32, 16, 8>,
        cudaFuncAttributeMaxDynamicSharedMemorySize, smem_total_c(32, 16, 8));
    cudaFuncSetAttribute((const void*)scnn_layer<16, 4, 32>,
        cudaFuncAttributeMaxDynamicSharedMemorySize, smem_total_c(16, 4, 32));

    build_B<<<1, NT>>>(sft, isft);

    scnn_layer<4, 16, 8><<<NB_TOTAL / 8, NT, smem_total_c(4, 16, 8)>>>(
        x, w1, bufA);
    scnn_layer<16, 32, 4><<<NB_TOTAL / 4, NT, smem_total_c(16, 32, 4)>>>(
        bufA, w2, bufB);
    scnn_layer<32, 64, 2><<<NB_TOTAL / 2, NT, smem_total_c(32, 64, 2)>>>(
        bufB, w3, bufA);
    scnn_layer<64, 32, 4><<<NB_TOTAL / 4, NT, smem_total_c(64, 32, 4)>>>(
        bufA, w4, bufB);
    scnn_layer<32, 16, 8><<<NB_TOTAL / 8, NT, smem_total_c(32, 16, 8)>>>(
        bufB, w5, bufA);
    scnn_layer<16, 4, 32><<<(NB_TOTAL + 31) / 32, NT, smem_total_c(16, 4, 32)>>>(
        bufA, w6, out);
}

// round 6
// speedup vs baseline: 2.3289x; 1.3714x over previous
#include <cuda_runtime.h>
#include <cuda_bf16.h>
#include <cstdint>
#include <cstddef>

// ----------------------------------------------------------------------------
// SCNN via warp-level HMMA (mma.sync bf16, fp32 accum), persistent-CTA form.
// Per CTA: one-time setup (B tiles, W, Y-pad zero), then loop over batch
// tiles: sconv(FFMA) -> GEMM1(HMMA) [+ overlap next-x load] -> GEMM2(HMMA)
// with direct gmem stores. 3 barriers per tile.
// ----------------------------------------------------------------------------

#define NB_TOTAL 50000
#define NC 45
#define ND 90
#define NT 512
#define GRID 148

#define YSTR   56   // Y row stride (bf16): 112B, conflict-free for ldmatrix
#define B1STR  56   // B1 [n=96][k=48]
#define B2STR 104   // B2 [n=48][k=96]: 208B
#define SIGSTR 104  // sig [m=128][p=96]

__device__ float g_bufA[(size_t)NB_TOTAL * 64 * NC];
__device__ float g_bufB[(size_t)NB_TOTAL * 32 * NC];
// Packed bf16 hi/lo B matrices, built once: B1=[n=96][k=48], B2=[n=48][k=96]
__device__ __nv_bfloat16 g_B1h[96 * 48], g_B1l[96 * 48];
__device__ __nv_bfloat16 g_B2h[48 * 96], g_B2l[48 * 96];

// ---------------- smem layout (bytes) ---------------------------------------
#define OFF_B1H 0
#define OFF_B1L 10752          /* +96*56*2  */
#define OFF_B2H 21504
#define OFF_B2L 31488          /* +48*104*2 */
#define OFF_YH  41472
#define OFF_YL  55808          /* +128*56*2 */
#define OFF_SGH 70144
#define OFF_SGL 96768          /* +128*104*2 */
#define OFF_X   123392
#define DYL 14336              /* OFF_YL - OFF_YH  */
#define DB1 10752              /* OFF_B1L - OFF_B1H */
#define DSG 26624              /* OFF_SGL - OFF_SGH */
#define DB2  9984              /* OFF_B2L - OFF_B2H */

__host__ __device__ constexpr int xstr_c(int CIN, int TB) { return TB * CIN + 4; }
__host__ __device__ constexpr int off_w_c(int CIN, int TB) {
    return OFF_X + NC * xstr_c(CIN, TB) * 4;
}
__host__ __device__ constexpr int smem_total_c(int CIN, int COUT, int TB) {
    return off_w_c(CIN, TB) + COUT * (CIN * 5 + 1) * 4;
}

// ---------------- PTX helpers ----------------------------------------------
__device__ __forceinline__ uint32_t smem_u32(const void* p) {
    uint32_t a;
    asm("{ .reg .u64 t; cvta.to.shared.u64 t, %1; cvt.u32.u64 %0, t; }"
        : "=r"(a) : "l"(p));
    return a;
}
__device__ __forceinline__ void ldsm_x4(uint32_t* r, uint32_t addr) {
    asm volatile("ldmatrix.sync.aligned.m8n8.x4.shared.b16 {%0,%1,%2,%3}, [%4];"
                 : "=r"(r[0]), "=r"(r[1]), "=r"(r[2]), "=r"(r[3]) : "r"(addr));
}
__device__ __forceinline__ void ldsm_x2(uint32_t* r, uint32_t addr) {
    asm volatile("ldmatrix.sync.aligned.m8n8.x2.shared.b16 {%0,%1}, [%2];"
                 : "=r"(r[0]), "=r"(r[1]) : "r"(addr));
}
__device__ __forceinline__ void mma_bf16(float* c, const uint32_t* a,
                                         uint32_t b0, uint32_t b1) {
    asm volatile(
        "mma.sync.aligned.m16n8k16.row.col.f32.bf16.bf16.f32 "
        "{%0,%1,%2,%3}, {%4,%5,%6,%7}, {%8,%9}, {%0,%1,%2,%3};"
        : "+f"(c[0]), "+f"(c[1]), "+f"(c[2]), "+f"(c[3])
        : "r"(a[0]), "r"(a[1]), "r"(a[2]), "r"(a[3]), "r"(b0), "r"(b1));
}
__device__ __forceinline__ uint32_t pack2bf(__nv_bfloat16 a, __nv_bfloat16 b) {
    return (uint32_t)__bfloat16_as_ushort(a) |
           ((uint32_t)__bfloat16_as_ushort(b) << 16);
}

// ---------------- problem constants -----------------------------------------
__host__ __device__ __forceinline__ constexpr int ggrp(int k) {
    return (k < 1) ? 0 : (k < 6) ? 1 : (k < 15) ? 2 : (k < 28) ? 3 : 4;
}
__device__ __forceinline__ float scl_of(int k) {
    const int g = ggrp(k);
    return g == 0 ? 1.77245385090552f
         : g == 1 ? 0.79266545952121f
         : g == 2 ? 0.59081795030184f
         : g == 3 ? 0.49159027f
         :          0.42988321f;
}

// ---------------- setup: pre-split B matrices to bf16 hi/lo -----------------
__global__ void build_B(const float* __restrict__ sft,
                        const float* __restrict__ isft) {
    const int tid = threadIdx.x;
    for (int i = tid; i < 96 * 48; i += NT) {      // B1[n=p(96)][k(48)]
        int n = i / 48, k = i - n * 48;
        float v = (n < ND && k < NC) ? isft[n * NC + k] : 0.f;
        __nv_bfloat16 hi = __float2bfloat16(v);
        g_B1h[i] = hi;
        g_B1l[i] = __float2bfloat16(v - __bfloat162float(hi));
    }
    for (int i = tid; i < 48 * 96; i += NT) {      // B2[n=k(48)][k=p(96)]
        int n = i / 96, p = i - n * 96;
        float v = (n < NC && p < ND) ? sft[n * ND + p] : 0.f;
        __nv_bfloat16 hi = __float2bfloat16(v);
        g_B2h[i] = hi;
        g_B2l[i] = __float2bfloat16(v - __bfloat162float(hi));
    }
}

// sconv over k in [K0,K0+KN): one thread, one row r; outputs bf16 hi/lo pairs.
template <int K0, int KN, int CIN, int XSTR>
__device__ __forceinline__ void sconv_seg(const float* __restrict__ xb,
                                          const float* __restrict__ wb,
                                          __nv_bfloat16* __restrict__ yh,
                                          __nv_bfloat16* __restrict__ yl,
                                          int r) {
    float acc[KN];
#pragma unroll
    for (int kk = 0; kk < KN; kk++) acc[kk] = 0.f;
#pragma unroll 1
    for (int cb = 0; cb < CIN; cb += 4) {
        float wv[4][5];
#pragma unroll
        for (int cc = 0; cc < 4; cc++)
#pragma unroll
            for (int g = 0; g < 5; g++) wv[cc][g] = wb[(cb + cc) * 5 + g];
#pragma unroll
        for (int kk = 0; kk < KN; kk++) {
            const float4 xv =
                *reinterpret_cast<const float4*>(xb + (K0 + kk) * XSTR + cb);
            const int g = ggrp(K0 + kk);
            acc[kk] = fmaf(xv.x, wv[0][g], acc[kk]);
            acc[kk] = fmaf(xv.y, wv[1][g], acc[kk]);
            acc[kk] = fmaf(xv.z, wv[2][g], acc[kk]);
            acc[kk] = fmaf(xv.w, wv[3][g], acc[kk]);
        }
    }
#pragma unroll
    for (int kk = 0; kk + 1 < KN; kk += 2) {
        const float v0 = acc[kk] * scl_of(K0 + kk);
        const float v1 = acc[kk + 1] * scl_of(K0 + kk + 1);
        const __nv_bfloat16 h0 = __float2bfloat16(v0);
        const __nv_bfloat16 h1 = __float2bfloat16(v1);
        const __nv_bfloat16 l0 = __float2bfloat16(v0 - __bfloat162float(h0));
        const __nv_bfloat16 l1 = __float2bfloat16(v1 - __bfloat162float(h1));
        *(uint32_t*)(yh + r * YSTR + K0 + kk) = pack2bf(h0, h1);
        *(uint32_t*)(yl + r * YSTR + K0 + kk) = pack2bf(l0, l1);
    }
    if constexpr (KN & 1) {
        const int k = K0 + KN - 1;
        const float v = acc[KN - 1] * scl_of(k);
        const __nv_bfloat16 h = __float2bfloat16(v);
        yh[r * YSTR + k] = h;
        yl[r * YSTR + k] = __float2bfloat16(v - __bfloat162float(h));
    }
}

// ---------------- per-layer persistent kernel -------------------------------
template <int CIN, int COUT, int TB>
__global__ void __launch_bounds__(NT, 1)
scnn_layer(const float* __restrict__ in, const float* __restrict__ w,
           float* __restrict__ out, int ntiles) {
    static_assert(TB * COUT == 128, "MOUT must be 128");
    static_assert(CIN % 4 == 0, "c-block");
    constexpr int MIN_ = TB * CIN;
    constexpr int XSTR = xstr_c(CIN, TB);
    constexpr int WSTR = CIN * 5 + 1;
    constexpr int OFF_W = off_w_c(CIN, TB);

    extern __shared__ char smc[];
    const uint32_t sb = smem_u32(smc);
    const int tid = threadIdx.x, wid = tid >> 5, lane = tid & 31;

    __nv_bfloat16* Yh  = (__nv_bfloat16*)(smc + OFF_YH);
    __nv_bfloat16* Yl  = (__nv_bfloat16*)(smc + OFF_YL);
    __nv_bfloat16* SGh = (__nv_bfloat16*)(smc + OFF_SGH);
    __nv_bfloat16* SGl = (__nv_bfloat16*)(smc + OFF_SGL);
    float* s_x = (float*)(smc + OFF_X);
    float* s_w = (float*)(smc + OFF_W);

    // ---- one-time setup: zero Y pads, copy B tiles, load W -----------------
    for (int i = tid; i < (OFF_SGH - OFF_YH) / 4; i += NT)
        ((uint32_t*)(smc + OFF_YH))[i] = 0;
    {
        const uint32_t* s1h = (const uint32_t*)g_B1h;
        const uint32_t* s1l = (const uint32_t*)g_B1l;
        uint32_t* d1h = (uint32_t*)(smc + OFF_B1H);
        uint32_t* d1l = (uint32_t*)(smc + OFF_B1L);
        for (int i = tid; i < 96 * 24; i += NT) {
            int n = i / 24, kk = i - n * 24;
            d1h[(n * B1STR) / 2 + kk] = s1h[i];
            d1l[(n * B1STR) / 2 + kk] = s1l[i];
        }
        const uint32_t* s2h = (const uint32_t*)g_B2h;
        const uint32_t* s2l = (const uint32_t*)g_B2l;
        uint32_t* d2h = (uint32_t*)(smc + OFF_B2H);
        uint32_t* d2l = (uint32_t*)(smc + OFF_B2L);
        for (int i = tid; i < 48 * 48; i += NT) {
            int n = i / 48, kk = i - n * 48;
            d2h[(n * B2STR) / 2 + kk] = s2h[i];
            d2l[(n * B2STR) / 2 + kk] = s2l[i];
        }
    }
    for (int i = tid; i < COUT * CIN * 5; i += NT) {
        int o = i / (CIN * 5);
        s_w[o * WSTR + (i - o * (CIN * 5))] = w[i];
    }

    // ---- loop-invariant per-thread addresses -------------------------------
    const int m0 = (wid >> 1) * 16;
    const int nb1 = (wid & 1) * 48;            // GEMM1 n-base
    const int nb2 = (wid & 1) * 24;            // GEMM2 n-base
    const int g = lane >> 3, rr = lane & 7;
    const uint32_t aY  = sb + OFF_YH +
        ((m0 + (g & 1) * 8 + rr) * YSTR + (g >> 1) * 8) * 2;
    const uint32_t bB1 = sb + OFF_B1H +
        ((nb1 + (g >> 1) * 8 + rr) * B1STR + (g & 1) * 8) * 2;
    const uint32_t aS  = sb + OFF_SGH +
        ((m0 + (g & 1) * 8 + rr) * SIGSTR + (g >> 1) * 8) * 2;
    const uint32_t bB2 = sb + OFF_B2H +
        ((nb2 + (g >> 1) * 8 + rr) * B2STR + (g & 1) * 8) * 2;
    const uint32_t bB2c = sb + OFF_B2H +
        ((nb2 + 16 + rr) * B2STR + (g & 1) * 8) * 2;
    const int qr = lane >> 2, qc = lane & 3;

    // sconv mapping (loop-invariant)
    const int rS = tid & 127;
    const int segS = tid >> 7;
    const float* xbS = s_x + (rS / COUT) * CIN;
    const float* wbS = s_w + (rS & (COUT - 1)) * WSTR;

    // ---- load first tile's x ----------------------------------------------
    int t = blockIdx.x;
    {
        const size_t base_in = (size_t)t * (MIN_ * NC);
        for (int i = tid; i < MIN_ * NC; i += NT) {
            int m = i / NC, k = i - m * NC;
            int b = t * TB + m / CIN;
            s_x[k * XSTR + m] = (b < NB_TOTAL) ? in[base_in + i] : 0.f;
        }
    }
    __syncthreads();

    // ---- persistent tile loop ----------------------------------------------
    for (; t < ntiles;) {
        const int tn = t + GRID;

        // phase A: sconv -> Y (bf16 hi/lo)
        if      (segS == 0) sconv_seg< 0, 12, CIN, XSTR>(xbS, wbS, Yh, Yl, rS);
        else if (segS == 1) sconv_seg<12, 12, CIN, XSTR>(xbS, wbS, Yh, Yl, rS);
        else if (segS == 2) sconv_seg<24, 12, CIN, XSTR>(xbS, wbS, Yh, Yl, rS);
        else                sconv_seg<36,  9, CIN, XSTR>(xbS, wbS, Yh, Yl, rS);
        __syncthreads();

        // phase B: GEMM1 sig = relu(Y * B1^T)  [+ overlap next x load]
        {
            float c[6][4];
#pragma unroll
            for (int i = 0; i < 6; i++)
#pragma unroll
                for (int j = 0; j < 4; j++) c[i][j] = 0.f;

#pragma unroll
            for (int ks = 0; ks < 3; ks++) {
                const uint32_t ao = aY + ks * 32;          // k0*2
                uint32_t ah[4], al[4];
                ldsm_x4(ah, ao);
                ldsm_x4(al, ao + DYL);
#pragma unroll
                for (int ntp = 0; ntp < 3; ntp++) {
                    const uint32_t bo = bB1 + ks * 32 + ntp * (16 * B1STR * 2);
                    uint32_t bh[4], bl[4];
                    ldsm_x4(bh, bo);
                    ldsm_x4(bl, bo + DB1);
                    mma_bf16(c[2 * ntp], ah, bh[0], bh[1]);
                    mma_bf16(c[2 * ntp], ah, bl[0], bl[1]);
                    mma_bf16(c[2 * ntp], al, bh[0], bh[1]);
                    mma_bf16(c[2 * ntp + 1], ah, bh[2], bh[3]);
                    mma_bf16(c[2 * ntp + 1], ah, bl[2], bl[3]);
                    mma_bf16(c[2 * ntp + 1], al, bh[2], bh[3]);
                }
            }
            // overlap: load next tile's x (x dead; Y/SIG untouched)
            if (tn < ntiles) {
                const size_t base_in = (size_t)tn * (MIN_ * NC);
                for (int i = tid; i < MIN_ * NC; i += NT) {
                    int m = i / NC, k = i - m * NC;
                    int b = tn * TB + m / CIN;
                    s_x[k * XSTR + m] = (b < NB_TOTAL) ? in[base_in + i] : 0.f;
                }
            }
            // epilogue: relu, hi/lo split, packed stores to sig
#pragma unroll
            for (int nt = 0; nt < 6; nt++) {
                const int col = nb1 + nt * 8 + 2 * qc;
#pragma unroll
                for (int half = 0; half < 2; half++) {
                    const int row = m0 + qr + 8 * half;
                    const float v0 = fmaxf(c[nt][2 * half], 0.f);
                    const float v1 = fmaxf(c[nt][2 * half + 1], 0.f);
                    const __nv_bfloat16 h0 = __float2bfloat16(v0);
                    const __nv_bfloat16 h1 = __float2bfloat16(v1);
                    const __nv_bfloat16 l0 =
                        __float2bfloat16(v0 - __bfloat162float(h0));
                    const __nv_bfloat16 l1 =
                        __float2bfloat16(v1 - __bfloat162float(h1));
                    *(uint32_t*)(SGh + row * SIGSTR + col) = pack2bf(h0, h1);
                    *(uint32_t*)(SGl + row * SIGSTR + col) = pack2bf(l0, l1);
                }
            }
        }
        __syncthreads();

        // phase C: GEMM2 out = sig * B2^T, fragments stored straight to gmem
        {
            float c[3][4];
#pragma unroll
            for (int i = 0; i < 3; i++)
#pragma unroll
                for (int j = 0; j < 4; j++) c[i][j] = 0.f;

#pragma unroll
            for (int ks = 0; ks < 6; ks++) {
                const uint32_t ao = aS + ks * 32;
                uint32_t ah[4], al[4];
                ldsm_x4(ah, ao);
                ldsm_x4(al, ao + DSG);
                {
                    const uint32_t bo = bB2 + ks * 32;
                    uint32_t bh[4], bl[4];
                    ldsm_x4(bh, bo);
                    ldsm_x4(bl, bo + DB2);
                    mma_bf16(c[0], ah, bh[0], bh[1]);
                    mma_bf16(c[0], ah, bl[0], bl[1]);
                    mma_bf16(c[0], al, bh[0], bh[1]);
                    mma_bf16(c[1], ah, bh[2], bh[3]);
                    mma_bf16(c[1], ah, bl[2], bl[3]);
                    mma_bf16(c[1], al, bh[2], bh[3]);
                }
                {
                    const uint32_t bo = bB2c + ks * 32;
                    uint32_t bh[2], bl[2];
                    ldsm_x2(bh, bo);
                    ldsm_x2(bl, bo + DB2);
                    mma_bf16(c[2], ah, bh[0], bh[1]);
                    mma_bf16(c[2], ah, bl[0], bl[1]);
                    mma_bf16(c[2], al, bh[0], bh[1]);
                }
            }
            // direct guarded stores (scalar, 32B-sector aligned per quad)
            const size_t base_out = (size_t)t * (128 * NC);
#pragma unroll
            for (int nt = 0; nt < 3; nt++) {
                const int col = nb2 + nt * 8 + 2 * qc;
#pragma unroll
                for (int half = 0; half < 2; half++) {
                    const int row = m0 + qr + 8 * half;
                    const int b = t * TB + row / COUT;
                    if (b < NB_TOTAL) {
                        const size_t idx = base_out + (size_t)row * NC + col;
                        if (col < NC)     out[idx]     = c[nt][2 * half];
                        if (col + 1 < NC) out[idx + 1] = c[nt][2 * half + 1];
                    }
                }
            }
        }
        __syncthreads();
        t = tn;
    }
}

// ---------------- host ------------------------------------------------------
extern "C" void kernel_launch(void* const* d_in, const int* in_sizes, int n_in,
                              void* d_out, int out_size) {
    (void)in_sizes; (void)n_in; (void)out_size;

    const float* x    = (const float*)d_in[0];
    const float* sft  = (const float*)d_in[1];
    const float* isft = (const float*)d_in[2];
    const float* w1   = (const float*)d_in[3];
    const float* w2   = (const float*)d_in[4];
    const float* w3   = (const float*)d_in[5];
    const float* w4   = (const float*)d_in[6];
    const float* w5   = (const float*)d_in[7];
    const float* w6   = (const float*)d_in[8];
    float* out = (float*)d_out;

    float *bufA = nullptr, *bufB = nullptr;
    cudaGetSymbolAddress((void**)&bufA, g_bufA);
    cudaGetSymbolAddress((void**)&bufB, g_bufB);

    cudaFuncSetAttribute((const void*)scnn_layer<4, 16, 8>,
        cudaFuncAttributeMaxDynamicSharedMemorySize, smem_total_c(4, 16, 8));
    cudaFuncSetAttribute((const void*)scnn_layer<16, 32, 4>,
        cudaFuncAttributeMaxDynamicSharedMemorySize, smem_total_c(16, 32, 4));
    cudaFuncSetAttribute((const void*)scnn_layer<32, 64, 2>,
        cudaFuncAttributeMaxDynamicSharedMemorySize, smem_total_c(32, 64, 2));
    cudaFuncSetAttribute((const void*)scnn_layer<64, 32, 4>,
        cudaFuncAttributeMaxDynamicSharedMemorySize, smem_total_c(64, 32, 4));
    cudaFuncSetAttribute((const void*)scnn_layer<32, 16, 8>,
        cudaFuncAttributeMaxDynamicSharedMemorySize, smem_total_c(32, 16, 8));
    cudaFuncSetAttribute((const void*)scnn_layer<16, 4, 32>,
        cudaFuncAttributeMaxDynamicSharedMemorySize, smem_total_c(16, 4, 32));

    build_B<<<1, NT>>>(sft, isft);

    scnn_layer<4, 16, 8><<<GRID, NT, smem_total_c(4, 16, 8)>>>(
        x, w1, bufA, NB_TOTAL / 8);
    scnn_layer<16, 32, 4><<<GRID, NT, smem_total_c(16, 32, 4)>>>(
        bufA, w2, bufB, NB_TOTAL / 4);
    scnn_layer<32, 64, 2><<<GRID, NT, smem_total_c(32, 64, 2)>>>(
        bufB, w3, bufA, NB_TOTAL / 2);
    scnn_layer<64, 32, 4><<<GRID, NT, smem_total_c(64, 32, 4)>>>(
        bufA, w4, bufB, NB_TOTAL / 4);
    scnn_layer<32, 16, 8><<<GRID, NT, smem_total_c(32, 16, 8)>>>(
        bufB, w5, bufA, NB_TOTAL / 8);
    scnn_layer<16, 4, 32><<<GRID, NT, smem_total_c(16, 4, 32)>>>(
        bufA, w6, out, (NB_TOTAL + 31) / 32);
}